// round 6
// baseline (speedup 1.0000x reference)
#include <cuda_runtime.h>
#include <cstddef>

#define B 8
#define L 2048
#define H 8
#define D 64
#define BH 64
#define SK 40
#define U  40
#define HD 512
#define SCALE 0.125f
#define NT 8            // key tiles of 256 rows
#define QC2 256         // probe queries per block
#define KSPLIT 8        // pv key splits
#define KT 256          // scores/pv key tile

// ---- device scratch ----
__device__ float g_M[BH * L];
__device__ int   g_top[BH * U];
__device__ float g_vmean[BH * D];
__device__ unsigned char g_ent[L * SK];
__device__ unsigned char g_off[L * (NT + 1)];
__device__ float g_scores[(size_t)BH * U * L];
__device__ float g_pv[BH * KSPLIT * U * D];

// ------------------------------------------------------------------
// Build per-q inverted sample lists bucketed by 256-row key tile,
// stable in s within each tile (deterministic accumulation order).
// ------------------------------------------------------------------
__global__ void k_build(const int* __restrict__ IS) {
    int q = blockIdx.x * blockDim.x + threadIdx.x;
    if (q >= L) return;
    int idxs[SK];
    int cnt[NT];
    #pragma unroll
    for (int t = 0; t < NT; ++t) cnt[t] = 0;
    #pragma unroll
    for (int s = 0; s < SK; ++s) {
        idxs[s] = IS[q * SK + s];
        cnt[idxs[s] >> 8]++;
    }
    int off[NT + 1];
    off[0] = 0;
    #pragma unroll
    for (int t = 0; t < NT; ++t) off[t + 1] = off[t] + cnt[t];
    #pragma unroll
    for (int t = 0; t <= NT; ++t) g_off[q * (NT + 1) + t] = (unsigned char)off[t];
    int pos[NT];
    #pragma unroll
    for (int t = 0; t < NT; ++t) pos[t] = off[t];
    #pragma unroll
    for (int s = 0; s < SK; ++s) {
        int t = idxs[s] >> 8;
        g_ent[q * SK + pos[t]++] = (unsigned char)(idxs[s] & 255);
    }
}

// ------------------------------------------------------------------
// Probe v7: smem-staged K tiles + register-resident Q.
// Warp owns 32 queries. Two 16-lane groups; group qh processes
// queries 2*jj+qh. Per entry: LDS.128 + 4 FMA + 4 group-masked
// shuffles (groups may diverge; masks cover only own converged half).
// Lane (lane&15)==jj keeps stats of its group's query.
// ------------------------------------------------------------------
__global__ __launch_bounds__(256, 2) void k_probe7(const float* __restrict__ Q,
                                                   const float* __restrict__ Kp) {
    extern __shared__ float ksm[];                  // 256 * 68 floats
    __shared__ unsigned char ent_sm[QC2 * SK];      // 10240 B
    __shared__ unsigned char off_sm[QC2 * (NT + 1)];// 2304 B
    float4* ksm4 = (float4*)ksm;                    // pitch 17 float4 (quad-stride 17: conflict-free)

    int bh = blockIdx.y, qc = blockIdx.x;
    int b = bh >> 3, h = bh & 7;
    int t = threadIdx.x, w = t >> 5, lane = t & 31;
    int qh = lane >> 4, li = lane & 15;
    unsigned gmask = 0xFFFFu << (qh << 4);
    int qbase0 = qc * QC2;

    {   // stage entry lists + offsets
        const uint4* esrc = (const uint4*)(g_ent + (size_t)qbase0 * SK);
        uint4* edst = (uint4*)ent_sm;
        for (int i = t; i < QC2 * SK / 16; i += 256) edst[i] = esrc[i];
        const unsigned* osrc = (const unsigned*)(g_off + (size_t)qbase0 * (NT + 1));
        unsigned* odst = (unsigned*)off_sm;
        for (int i = t; i < QC2 * (NT + 1) / 4; i += 256) odst[i] = osrc[i];
    }

    // Q fragments: lane li holds float4 chunk li of its group's 16 queries
    float4 qv[16];
    #pragma unroll
    for (int jj = 0; jj < 16; ++jj) {
        int qg = qbase0 + w * 32 + 2 * jj + qh;
        qv[jj] = *(const float4*)(Q + (size_t)(b * L + qg) * HD + h * D + 4 * li);
    }
    float mxr = -3.4e38f, smr = 0.f;

    const float4* Ksrc0 = (const float4*)(Kp + (size_t)(b * L) * HD + h * D);

    for (int kt = 0; kt < NT; ++kt) {
        __syncthreads();
        const float4* src = Ksrc0 + (size_t)(kt * 256) * (HD / 4);
        for (int i = t; i < 256 * 16; i += 256) {
            int r = i >> 4, c = i & 15;
            ksm4[r * 17 + c] = src[(size_t)r * (HD / 4) + c];
        }
        __syncthreads();

        #pragma unroll
        for (int jj = 0; jj < 16; ++jj) {
            int qloc = w * 32 + 2 * jj + qh;                 // group-uniform
            int o0 = off_sm[qloc * (NT + 1) + kt];
            int o1 = off_sm[qloc * (NT + 1) + kt + 1];
            const unsigned char* ep = ent_sm + qloc * SK;
            float lmx = -3.4e38f, lsm = 0.f;
            int e = o0;
            for (; e + 2 <= o1; e += 2) {      // two independent chains
                int ka = ep[e], kb = ep[e + 1];
                float4 va = ksm4[ka * 17 + li];
                float4 vb = ksm4[kb * 17 + li];
                float pa = qv[jj].x * va.x; pa = fmaf(qv[jj].y, va.y, pa);
                pa = fmaf(qv[jj].z, va.z, pa); pa = fmaf(qv[jj].w, va.w, pa);
                float pb = qv[jj].x * vb.x; pb = fmaf(qv[jj].y, vb.y, pb);
                pb = fmaf(qv[jj].z, vb.z, pb); pb = fmaf(qv[jj].w, vb.w, pb);
                #pragma unroll
                for (int o = 1; o <= 8; o <<= 1) {
                    pa += __shfl_xor_sync(gmask, pa, o);
                    pb += __shfl_xor_sync(gmask, pb, o);
                }
                lmx = fmaxf(lmx, fmaxf(pa, pb));
                lsm += pa + pb;
            }
            if (e < o1) {
                int ka = ep[e];
                float4 va = ksm4[ka * 17 + li];
                float pa = qv[jj].x * va.x; pa = fmaf(qv[jj].y, va.y, pa);
                pa = fmaf(qv[jj].z, va.z, pa); pa = fmaf(qv[jj].w, va.w, pa);
                #pragma unroll
                for (int o = 1; o <= 8; o <<= 1)
                    pa += __shfl_xor_sync(gmask, pa, o);
                lmx = fmaxf(lmx, pa);
                lsm += pa;
            }
            if (li == jj) { mxr = fmaxf(mxr, lmx); smr += lsm; }
        }
    }
    // lane (qh, li) holds stats for query w*32 + 2*li + qh
    int qout = qbase0 + w * 32 + 2 * li + qh;
    g_M[bh * L + qout] = mxr - smr * (1.f / SK);
}

// ------------------------------------------------------------------
// V mean per (b,h,d)
// ------------------------------------------------------------------
__global__ void k_vmean(const float* __restrict__ V) {
    __shared__ float smem[4 * 64];
    int bh = blockIdx.x; int b = bh >> 3, h = bh & 7;
    int d = threadIdx.x & 63, p = threadIdx.x >> 6;
    float s = 0.f;
    for (int l = p; l < L; l += 4)
        s += V[(size_t)(b * L + l) * HD + h * D + d];
    smem[p * 64 + d] = s;
    __syncthreads();
    if (threadIdx.x < 64) {
        float t = smem[threadIdx.x] + smem[64 + threadIdx.x]
                + smem[128 + threadIdx.x] + smem[192 + threadIdx.x];
        g_vmean[bh * 64 + threadIdx.x] = t * (1.f / L);
    }
}

// ------------------------------------------------------------------
// Top-40 per (b,h): phase 1 = 8 warps extract slice top-40 (regs);
// phase 2 = rank selection over 320 unique candidates (order-free:
// the output scatter is index-set based, so g_top order is irrelevant).
// ------------------------------------------------------------------
__global__ void k_topk4() {
    __shared__ unsigned long long cand[8 * U];
    int bh = blockIdx.x;
    int t = threadIdx.x, w = t >> 5, lane = t & 31;

    unsigned long long k[8];
    #pragma unroll
    for (int j = 0; j < 8; ++j) {
        int i = w * 256 + j * 32 + lane;
        unsigned bits = __float_as_uint(g_M[bh * L + i]);
        bits = (bits & 0x80000000u) ? ~bits : (bits | 0x80000000u);
        k[j] = ((unsigned long long)bits << 32) | (unsigned)(L - 1 - i);
    }
    for (int it = 0; it < U; ++it) {
        unsigned long long lm = k[0];
        #pragma unroll
        for (int j = 1; j < 8; ++j) if (k[j] > lm) lm = k[j];
        unsigned long long wm = lm;
        #pragma unroll
        for (int o = 16; o; o >>= 1) {
            unsigned long long x = __shfl_xor_sync(0xffffffffu, wm, o);
            if (x > wm) wm = x;
        }
        if (lane == 0) cand[w * U + it] = wm;
        #pragma unroll
        for (int j = 0; j < 8; ++j) if (k[j] == wm) k[j] = 0ull;
    }
    __syncthreads();
    for (int i = t; i < 8 * U; i += 256) {
        unsigned long long me = cand[i];
        int rank = 0;
        for (int j = 0; j < 8 * U; ++j) rank += (cand[j] > me) ? 1 : 0;
        if (rank < U)
            g_top[bh * U + rank] = (L - 1) - (int)(me & 0xffffffffu);
    }
}

// ------------------------------------------------------------------
// Fill output with broadcast V-mean
// ------------------------------------------------------------------
__global__ void k_fill(float* __restrict__ out) {
    int i4 = blockIdx.x * blockDim.x + threadIdx.x;
    int linear = i4 * 4;
    int d = linear & 63;
    int h = (linear >> 6) & 7;
    int b = linear >> 20;
    float4 v = *(const float4*)&g_vmean[(b * 8 + h) * 64 + d];
    *(float4*)(out + linear) = v;
}

// ------------------------------------------------------------------
// Scores: float4 smem reads, pitch 68 (conflict-free per phase)
// ------------------------------------------------------------------
__global__ void k_scores(const float* __restrict__ Q, const float* __restrict__ Kp) {
    extern __shared__ float smem[];
    float* Ksm = smem;               // KT * 68
    float* Qsm = smem + KT * 68;     // U * 64
    int bh = blockIdx.y, kt = blockIdx.x;
    int b = bh >> 3, h = bh & 7;
    int k0 = kt * KT;
    int t = threadIdx.x;             // 512

    for (int i4 = t; i4 < U * 16; i4 += 512) {
        int u = i4 >> 4, d4 = (i4 & 15) * 4;
        int qidx = g_top[bh * U + u];
        *(float4*)&Qsm[u * 64 + d4] =
            *(const float4*)&Q[(size_t)(b * L + qidx) * HD + h * D + d4];
    }
    for (int i4 = t; i4 < KT * 16; i4 += 512) {
        int k = i4 >> 4, d4 = (i4 & 15) * 4;
        *(float4*)&Ksm[k * 68 + d4] =
            *(const float4*)&Kp[(size_t)(b * L + k0 + k) * HD + h * D + d4];
    }
    __syncthreads();

    int kg = t & 63, ug = t >> 6;
    int u0 = ug * 5;
    float acc[5][4];
    #pragma unroll
    for (int i = 0; i < 5; ++i)
        #pragma unroll
        for (int j = 0; j < 4; ++j) acc[i][j] = 0.f;

    for (int d = 0; d < 64; d += 4) {
        float4 k4[4], q4[5];
        #pragma unroll
        for (int j = 0; j < 4; ++j) k4[j] = *(float4*)&Ksm[(kg + 64 * j) * 68 + d];
        #pragma unroll
        for (int i = 0; i < 5; ++i) q4[i] = *(float4*)&Qsm[(u0 + i) * 64 + d];
        #pragma unroll
        for (int i = 0; i < 5; ++i)
            #pragma unroll
            for (int j = 0; j < 4; ++j) {
                acc[i][j] = fmaf(q4[i].x, k4[j].x, acc[i][j]);
                acc[i][j] = fmaf(q4[i].y, k4[j].y, acc[i][j]);
                acc[i][j] = fmaf(q4[i].z, k4[j].z, acc[i][j]);
                acc[i][j] = fmaf(q4[i].w, k4[j].w, acc[i][j]);
            }
    }
    #pragma unroll
    for (int i = 0; i < 5; ++i)
        #pragma unroll
        for (int j = 0; j < 4; ++j)
            g_scores[(size_t)(bh * U + u0 + i) * L + k0 + kg + 64 * j] = acc[i][j] * SCALE;
}

// ------------------------------------------------------------------
// Row softmax over 2048, in place
// ------------------------------------------------------------------
__global__ void k_softmax() {
    __shared__ float red[8];
    size_t row = blockIdx.x;
    float* p = g_scores + row * L;
    int t = threadIdx.x, lane = t & 31, w = t >> 5;
    float4 v0 = *(float4*)&p[4 * t];
    float4 v1 = *(float4*)&p[4 * (t + 256)];
    float m = fmaxf(fmaxf(fmaxf(v0.x, v0.y), fmaxf(v0.z, v0.w)),
                    fmaxf(fmaxf(v1.x, v1.y), fmaxf(v1.z, v1.w)));
    #pragma unroll
    for (int o = 16; o; o >>= 1) m = fmaxf(m, __shfl_xor_sync(0xffffffffu, m, o));
    if (lane == 0) red[w] = m;
    __syncthreads();
    m = red[0];
    #pragma unroll
    for (int i = 1; i < 8; ++i) m = fmaxf(m, red[i]);
    __syncthreads();

    v0.x = __expf(v0.x - m); v0.y = __expf(v0.y - m);
    v0.z = __expf(v0.z - m); v0.w = __expf(v0.w - m);
    v1.x = __expf(v1.x - m); v1.y = __expf(v1.y - m);
    v1.z = __expf(v1.z - m); v1.w = __expf(v1.w - m);
    float s = v0.x + v0.y + v0.z + v0.w + v1.x + v1.y + v1.z + v1.w;
    #pragma unroll
    for (int o = 16; o; o >>= 1) s += __shfl_xor_sync(0xffffffffu, s, o);
    if (lane == 0) red[w] = s;
    __syncthreads();
    s = red[0];
    #pragma unroll
    for (int i = 1; i < 8; ++i) s += red[i];
    float inv = 1.f / s;
    v0.x *= inv; v0.y *= inv; v0.z *= inv; v0.w *= inv;
    v1.x *= inv; v1.y *= inv; v1.z *= inv; v1.w *= inv;
    *(float4*)&p[4 * t] = v0;
    *(float4*)&p[4 * (t + 256)] = v1;
}

// ------------------------------------------------------------------
// Partial PV per 256-key split
// ------------------------------------------------------------------
__global__ void k_pv(const float* __restrict__ V) {
    extern __shared__ float smem[];
    float* Vsm = smem;               // KT * 64
    float* Asm = smem + KT * 64;     // U * 260
    int bh = blockIdx.y, ks = blockIdx.x;
    int b = bh >> 3, h = bh & 7;
    int k0 = ks * KT;
    int t = threadIdx.x;             // 128

    for (int i4 = t; i4 < U * (KT / 4); i4 += 128) {
        int u = i4 >> 6, k4 = (i4 & 63) * 4;
        *(float4*)&Asm[u * 260 + k4] =
            *(const float4*)&g_scores[(size_t)(bh * U + u) * L + k0 + k4];
    }
    for (int i4 = t; i4 < KT * 16; i4 += 128) {
        int k = i4 >> 4, d4 = (i4 & 15) * 4;
        *(float4*)&Vsm[k * 64 + d4] =
            *(const float4*)&V[(size_t)(b * L + k0 + k) * HD + h * D + d4];
    }
    __syncthreads();

    int ug = t & 7, dg = t >> 3;
    int u0 = ug * 5, d0 = dg * 4;
    float4 acc[5];
    #pragma unroll
    for (int i = 0; i < 5; ++i) acc[i] = make_float4(0.f, 0.f, 0.f, 0.f);

    #pragma unroll 2
    for (int k = 0; k < KT; ++k) {
        float4 v = *(float4*)&Vsm[k * 64 + d0];
        #pragma unroll
        for (int i = 0; i < 5; ++i) {
            float a = Asm[(u0 + i) * 260 + k];
            acc[i].x = fmaf(a, v.x, acc[i].x);
            acc[i].y = fmaf(a, v.y, acc[i].y);
            acc[i].z = fmaf(a, v.z, acc[i].z);
            acc[i].w = fmaf(a, v.w, acc[i].w);
        }
    }
    #pragma unroll
    for (int i = 0; i < 5; ++i)
        *(float4*)&g_pv[(size_t)((bh * KSPLIT + ks) * U + u0 + i) * D + d0] = acc[i];
}

// ------------------------------------------------------------------
// Reduce partials, scatter to output
// ------------------------------------------------------------------
__global__ void k_final(float* __restrict__ out) {
    int i4 = blockIdx.x * blockDim.x + threadIdx.x;
    if (i4 >= BH * U * 16) return;
    int d4 = (i4 & 15) * 4;
    int u  = (i4 >> 4) % U;
    int bh = i4 / (U * 16);
    float4 s = make_float4(0.f, 0.f, 0.f, 0.f);
    #pragma unroll
    for (int ks = 0; ks < KSPLIT; ++ks) {
        float4 p = *(const float4*)&g_pv[(size_t)((bh * KSPLIT + ks) * U + u) * D + d4];
        s.x += p.x; s.y += p.y; s.z += p.z; s.w += p.w;
    }
    int q = g_top[bh * U + u];
    int b = bh >> 3, h = bh & 7;
    *(float4*)&out[(size_t)(b * L + q) * HD + h * D + d4] = s;
}

// ------------------------------------------------------------------
extern "C" void kernel_launch(void* const* d_in, const int* in_sizes, int n_in,
                              void* d_out, int out_size) {
    const float* Q = (const float*)d_in[0];
    const float* K = (const float*)d_in[1];
    const float* V = (const float*)d_in[2];
    const int*  IS = (const int*)d_in[3];
    float* out = (float*)d_out;

    const int smem_probe  = 256 * 68 * 4;                  // 69632 (dynamic)
    const int smem_scores = (KT * 68 + U * 64) * 4;        // 79872
    const int smem_pv     = (KT * 64 + U * 260) * 4;       // 107136
    cudaFuncSetAttribute(k_probe7, cudaFuncAttributeMaxDynamicSharedMemorySize, smem_probe);
    cudaFuncSetAttribute(k_scores, cudaFuncAttributeMaxDynamicSharedMemorySize, smem_scores);
    cudaFuncSetAttribute(k_pv,     cudaFuncAttributeMaxDynamicSharedMemorySize, smem_pv);

    k_build  <<<(L + 255) / 256, 256>>>(IS);
    k_vmean  <<<BH, 256>>>(V);
    k_probe7 <<<dim3(L / QC2, BH), 256, smem_probe>>>(Q, K);
    k_topk4  <<<BH, 256>>>();
    k_fill   <<<(B * L * HD / 4) / 256, 256>>>(out);
    k_scores <<<dim3(L / KT, BH), 512, smem_scores>>>(Q, K);
    k_softmax<<<BH * U, 256>>>();
    k_pv     <<<dim3(L / KT, BH), 128, smem_pv>>>(V);
    k_final  <<<(BH * U * 16 + 255) / 256, 256>>>(out);
}

// round 7
// speedup vs baseline: 1.1373x; 1.1373x over previous
#include <cuda_runtime.h>
#include <cstddef>

#define B 8
#define L 2048
#define H 8
#define D 64
#define BH 64
#define SK 40
#define U  40
#define HD 512
#define SCALE 0.125f
#define NT 8            // key tiles of 256 rows
#define QC2 256         // probe queries per block
#define KSPLIT 8        // pv key splits
#define KT 256          // scores/pv key tile

// ---- device scratch ----
__device__ float g_M[BH * L];
__device__ int   g_top[BH * U];
__device__ float g_vmean[BH * D];
__device__ unsigned char g_ent[L * SK];
__device__ unsigned char g_off[L * (NT + 1)];
__device__ float g_scores[(size_t)BH * U * L];
__device__ float g_pv[BH * KSPLIT * U * D];

// ------------------------------------------------------------------
// Build per-q inverted sample lists bucketed by 256-row key tile,
// stable in s within each tile (deterministic accumulation order).
// ------------------------------------------------------------------
__global__ void k_build(const int* __restrict__ IS) {
    int q = blockIdx.x * blockDim.x + threadIdx.x;
    if (q >= L) return;
    int idxs[SK];
    int cnt[NT];
    #pragma unroll
    for (int t = 0; t < NT; ++t) cnt[t] = 0;
    #pragma unroll
    for (int s = 0; s < SK; ++s) {
        idxs[s] = IS[q * SK + s];
        cnt[idxs[s] >> 8]++;
    }
    int off[NT + 1];
    off[0] = 0;
    #pragma unroll
    for (int t = 0; t < NT; ++t) off[t + 1] = off[t] + cnt[t];
    #pragma unroll
    for (int t = 0; t <= NT; ++t) g_off[q * (NT + 1) + t] = (unsigned char)off[t];
    int pos[NT];
    #pragma unroll
    for (int t = 0; t < NT; ++t) pos[t] = off[t];
    #pragma unroll
    for (int s = 0; s < SK; ++s) {
        int t = idxs[s] >> 8;
        g_ent[q * SK + pos[t]++] = (unsigned char)(idxs[s] & 255);
    }
}

// ------------------------------------------------------------------
// Probe v8: thread-per-query, NO cross-lane ops anywhere.
// K tiles staged in smem (pitch 17 float4). Thread's Q row lives in
// 16 float4 registers. Per entry: 16 independent LDS.128 + 64 FMA.
// ------------------------------------------------------------------
__global__ __launch_bounds__(256, 2) void k_probe8(const float* __restrict__ Q,
                                                   const float* __restrict__ Kp) {
    extern __shared__ float ksm[];                   // 256 * 68 floats
    __shared__ unsigned char ent_sm[QC2 * SK];       // 10240 B
    __shared__ unsigned char off_sm[QC2 * (NT + 1)]; // 2304 B
    float4* ksm4 = (float4*)ksm;                     // row pitch 17 float4

    int bh = blockIdx.y, qc = blockIdx.x;
    int b = bh >> 3, h = bh & 7;
    int t = threadIdx.x;
    int qbase0 = qc * QC2;

    {   // stage entry lists + offsets
        const uint4* esrc = (const uint4*)(g_ent + (size_t)qbase0 * SK);
        uint4* edst = (uint4*)ent_sm;
        for (int i = t; i < QC2 * SK / 16; i += 256) edst[i] = esrc[i];
        const unsigned* osrc = (const unsigned*)(g_off + (size_t)qbase0 * (NT + 1));
        unsigned* odst = (unsigned*)off_sm;
        for (int i = t; i < QC2 * (NT + 1) / 4; i += 256) odst[i] = osrc[i];
    }

    // Q row of this thread's query -> 16 float4 registers
    float4 qv[16];
    {
        const float4* qrow = (const float4*)(Q + (size_t)(b * L + qbase0 + t) * HD + h * D);
        #pragma unroll
        for (int c = 0; c < 16; ++c) qv[c] = qrow[c];
    }

    float mx = -3.4e38f, sm = 0.f;
    const float4* Ksrc0 = (const float4*)(Kp + (size_t)(b * L) * HD + h * D);

    for (int kt = 0; kt < NT; ++kt) {
        __syncthreads();
        const float4* src = Ksrc0 + (size_t)(kt * 256) * (HD / 4);
        for (int i = t; i < 256 * 16; i += 256) {
            int r = i >> 4, c = i & 15;
            ksm4[r * 17 + c] = src[(size_t)r * (HD / 4) + c];
        }
        __syncthreads();

        int o0 = off_sm[t * (NT + 1) + kt];
        int o1 = off_sm[t * (NT + 1) + kt + 1];
        const unsigned char* ep = ent_sm + t * SK;
        for (int e = o0; e < o1; ++e) {
            int kl = ep[e];
            const float4* kr = &ksm4[kl * 17];
            float a0 = 0.f, a1 = 0.f, a2 = 0.f, a3 = 0.f;
            #pragma unroll
            for (int c = 0; c < 16; c += 4) {
                float4 k0 = kr[c], k1 = kr[c + 1], k2 = kr[c + 2], k3 = kr[c + 3];
                a0 = fmaf(qv[c].x,     k0.x, a0); a0 = fmaf(qv[c].y,     k0.y, a0);
                a0 = fmaf(qv[c].z,     k0.z, a0); a0 = fmaf(qv[c].w,     k0.w, a0);
                a1 = fmaf(qv[c + 1].x, k1.x, a1); a1 = fmaf(qv[c + 1].y, k1.y, a1);
                a1 = fmaf(qv[c + 1].z, k1.z, a1); a1 = fmaf(qv[c + 1].w, k1.w, a1);
                a2 = fmaf(qv[c + 2].x, k2.x, a2); a2 = fmaf(qv[c + 2].y, k2.y, a2);
                a2 = fmaf(qv[c + 2].z, k2.z, a2); a2 = fmaf(qv[c + 2].w, k2.w, a2);
                a3 = fmaf(qv[c + 3].x, k3.x, a3); a3 = fmaf(qv[c + 3].y, k3.y, a3);
                a3 = fmaf(qv[c + 3].z, k3.z, a3); a3 = fmaf(qv[c + 3].w, k3.w, a3);
            }
            float p = (a0 + a1) + (a2 + a3);
            mx = fmaxf(mx, p);
            sm += p;
        }
    }
    g_M[bh * L + qbase0 + t] = mx - sm * (1.f / SK);
}

// ------------------------------------------------------------------
// V mean per (b,h,d)
// ------------------------------------------------------------------
__global__ void k_vmean(const float* __restrict__ V) {
    __shared__ float smem[4 * 64];
    int bh = blockIdx.x; int b = bh >> 3, h = bh & 7;
    int d = threadIdx.x & 63, p = threadIdx.x >> 6;
    float s = 0.f;
    for (int l = p; l < L; l += 4)
        s += V[(size_t)(b * L + l) * HD + h * D + d];
    smem[p * 64 + d] = s;
    __syncthreads();
    if (threadIdx.x < 64) {
        float t = smem[threadIdx.x] + smem[64 + threadIdx.x]
                + smem[128 + threadIdx.x] + smem[192 + threadIdx.x];
        g_vmean[bh * 64 + threadIdx.x] = t * (1.f / L);
    }
}

// ------------------------------------------------------------------
// Top-40 per (b,h): phase 1 = 8 warps extract slice top-40 (regs);
// phase 2 = rank selection over 320 unique candidates (order-free:
// the output scatter is index-set based, so g_top order is irrelevant).
// ------------------------------------------------------------------
__global__ void k_topk4() {
    __shared__ unsigned long long cand[8 * U];
    int bh = blockIdx.x;
    int t = threadIdx.x, w = t >> 5, lane = t & 31;

    unsigned long long k[8];
    #pragma unroll
    for (int j = 0; j < 8; ++j) {
        int i = w * 256 + j * 32 + lane;
        unsigned bits = __float_as_uint(g_M[bh * L + i]);
        bits = (bits & 0x80000000u) ? ~bits : (bits | 0x80000000u);
        k[j] = ((unsigned long long)bits << 32) | (unsigned)(L - 1 - i);
    }
    for (int it = 0; it < U; ++it) {
        unsigned long long lm = k[0];
        #pragma unroll
        for (int j = 1; j < 8; ++j) if (k[j] > lm) lm = k[j];
        unsigned long long wm = lm;
        #pragma unroll
        for (int o = 16; o; o >>= 1) {
            unsigned long long x = __shfl_xor_sync(0xffffffffu, wm, o);
            if (x > wm) wm = x;
        }
        if (lane == 0) cand[w * U + it] = wm;
        #pragma unroll
        for (int j = 0; j < 8; ++j) if (k[j] == wm) k[j] = 0ull;
    }
    __syncthreads();
    for (int i = t; i < 8 * U; i += 256) {
        unsigned long long me = cand[i];
        int rank = 0;
        for (int j = 0; j < 8 * U; ++j) rank += (cand[j] > me) ? 1 : 0;
        if (rank < U)
            g_top[bh * U + rank] = (L - 1) - (int)(me & 0xffffffffu);
    }
}

// ------------------------------------------------------------------
// Fill output with broadcast V-mean
// ------------------------------------------------------------------
__global__ void k_fill(float* __restrict__ out) {
    int i4 = blockIdx.x * blockDim.x + threadIdx.x;
    int linear = i4 * 4;
    int d = linear & 63;
    int h = (linear >> 6) & 7;
    int b = linear >> 20;
    float4 v = *(const float4*)&g_vmean[(b * 8 + h) * 64 + d];
    *(float4*)(out + linear) = v;
}

// ------------------------------------------------------------------
// Scores: float4 smem reads, pitch 68 (conflict-free per phase)
// ------------------------------------------------------------------
__global__ void k_scores(const float* __restrict__ Q, const float* __restrict__ Kp) {
    extern __shared__ float smem[];
    float* Ksm = smem;               // KT * 68
    float* Qsm = smem + KT * 68;     // U * 64
    int bh = blockIdx.y, kt = blockIdx.x;
    int b = bh >> 3, h = bh & 7;
    int k0 = kt * KT;
    int t = threadIdx.x;             // 512

    for (int i4 = t; i4 < U * 16; i4 += 512) {
        int u = i4 >> 4, d4 = (i4 & 15) * 4;
        int qidx = g_top[bh * U + u];
        *(float4*)&Qsm[u * 64 + d4] =
            *(const float4*)&Q[(size_t)(b * L + qidx) * HD + h * D + d4];
    }
    for (int i4 = t; i4 < KT * 16; i4 += 512) {
        int k = i4 >> 4, d4 = (i4 & 15) * 4;
        *(float4*)&Ksm[k * 68 + d4] =
            *(const float4*)&Kp[(size_t)(b * L + k0 + k) * HD + h * D + d4];
    }
    __syncthreads();

    int kg = t & 63, ug = t >> 6;
    int u0 = ug * 5;
    float acc[5][4];
    #pragma unroll
    for (int i = 0; i < 5; ++i)
        #pragma unroll
        for (int j = 0; j < 4; ++j) acc[i][j] = 0.f;

    for (int d = 0; d < 64; d += 4) {
        float4 k4[4], q4[5];
        #pragma unroll
        for (int j = 0; j < 4; ++j) k4[j] = *(float4*)&Ksm[(kg + 64 * j) * 68 + d];
        #pragma unroll
        for (int i = 0; i < 5; ++i) q4[i] = *(float4*)&Qsm[(u0 + i) * 64 + d];
        #pragma unroll
        for (int i = 0; i < 5; ++i)
            #pragma unroll
            for (int j = 0; j < 4; ++j) {
                acc[i][j] = fmaf(q4[i].x, k4[j].x, acc[i][j]);
                acc[i][j] = fmaf(q4[i].y, k4[j].y, acc[i][j]);
                acc[i][j] = fmaf(q4[i].z, k4[j].z, acc[i][j]);
                acc[i][j] = fmaf(q4[i].w, k4[j].w, acc[i][j]);
            }
    }
    #pragma unroll
    for (int i = 0; i < 5; ++i)
        #pragma unroll
        for (int j = 0; j < 4; ++j)
            g_scores[(size_t)(bh * U + u0 + i) * L + k0 + kg + 64 * j] = acc[i][j] * SCALE;
}

// ------------------------------------------------------------------
// Row softmax over 2048, in place
// ------------------------------------------------------------------
__global__ void k_softmax() {
    __shared__ float red[8];
    size_t row = blockIdx.x;
    float* p = g_scores + row * L;
    int t = threadIdx.x, lane = t & 31, w = t >> 5;
    float4 v0 = *(float4*)&p[4 * t];
    float4 v1 = *(float4*)&p[4 * (t + 256)];
    float m = fmaxf(fmaxf(fmaxf(v0.x, v0.y), fmaxf(v0.z, v0.w)),
                    fmaxf(fmaxf(v1.x, v1.y), fmaxf(v1.z, v1.w)));
    #pragma unroll
    for (int o = 16; o; o >>= 1) m = fmaxf(m, __shfl_xor_sync(0xffffffffu, m, o));
    if (lane == 0) red[w] = m;
    __syncthreads();
    m = red[0];
    #pragma unroll
    for (int i = 1; i < 8; ++i) m = fmaxf(m, red[i]);
    __syncthreads();

    v0.x = __expf(v0.x - m); v0.y = __expf(v0.y - m);
    v0.z = __expf(v0.z - m); v0.w = __expf(v0.w - m);
    v1.x = __expf(v1.x - m); v1.y = __expf(v1.y - m);
    v1.z = __expf(v1.z - m); v1.w = __expf(v1.w - m);
    float s = v0.x + v0.y + v0.z + v0.w + v1.x + v1.y + v1.z + v1.w;
    #pragma unroll
    for (int o = 16; o; o >>= 1) s += __shfl_xor_sync(0xffffffffu, s, o);
    if (lane == 0) red[w] = s;
    __syncthreads();
    s = red[0];
    #pragma unroll
    for (int i = 1; i < 8; ++i) s += red[i];
    float inv = 1.f / s;
    v0.x *= inv; v0.y *= inv; v0.z *= inv; v0.w *= inv;
    v1.x *= inv; v1.y *= inv; v1.z *= inv; v1.w *= inv;
    *(float4*)&p[4 * t] = v0;
    *(float4*)&p[4 * (t + 256)] = v1;
}

// ------------------------------------------------------------------
// Partial PV per 256-key split
// ------------------------------------------------------------------
__global__ void k_pv(const float* __restrict__ V) {
    extern __shared__ float smem[];
    float* Vsm = smem;               // KT * 64
    float* Asm = smem + KT * 64;     // U * 260
    int bh = blockIdx.y, ks = blockIdx.x;
    int b = bh >> 3, h = bh & 7;
    int k0 = ks * KT;
    int t = threadIdx.x;             // 128

    for (int i4 = t; i4 < U * (KT / 4); i4 += 128) {
        int u = i4 >> 6, k4 = (i4 & 63) * 4;
        *(float4*)&Asm[u * 260 + k4] =
            *(const float4*)&g_scores[(size_t)(bh * U + u) * L + k0 + k4];
    }
    for (int i4 = t; i4 < KT * 16; i4 += 128) {
        int k = i4 >> 4, d4 = (i4 & 15) * 4;
        *(float4*)&Vsm[k * 64 + d4] =
            *(const float4*)&V[(size_t)(b * L + k0 + k) * HD + h * D + d4];
    }
    __syncthreads();

    int ug = t & 7, dg = t >> 3;
    int u0 = ug * 5, d0 = dg * 4;
    float4 acc[5];
    #pragma unroll
    for (int i = 0; i < 5; ++i) acc[i] = make_float4(0.f, 0.f, 0.f, 0.f);

    #pragma unroll 2
    for (int k = 0; k < KT; ++k) {
        float4 v = *(float4*)&Vsm[k * 64 + d0];
        #pragma unroll
        for (int i = 0; i < 5; ++i) {
            float a = Asm[(u0 + i) * 260 + k];
            acc[i].x = fmaf(a, v.x, acc[i].x);
            acc[i].y = fmaf(a, v.y, acc[i].y);
            acc[i].z = fmaf(a, v.z, acc[i].z);
            acc[i].w = fmaf(a, v.w, acc[i].w);
        }
    }
    #pragma unroll
    for (int i = 0; i < 5; ++i)
        *(float4*)&g_pv[(size_t)((bh * KSPLIT + ks) * U + u0 + i) * D + d0] = acc[i];
}

// ------------------------------------------------------------------
// Reduce partials, scatter to output
// ------------------------------------------------------------------
__global__ void k_final(float* __restrict__ out) {
    int i4 = blockIdx.x * blockDim.x + threadIdx.x;
    if (i4 >= BH * U * 16) return;
    int d4 = (i4 & 15) * 4;
    int u  = (i4 >> 4) % U;
    int bh = i4 / (U * 16);
    float4 s = make_float4(0.f, 0.f, 0.f, 0.f);
    #pragma unroll
    for (int ks = 0; ks < KSPLIT; ++ks) {
        float4 p = *(const float4*)&g_pv[(size_t)((bh * KSPLIT + ks) * U + u) * D + d4];
        s.x += p.x; s.y += p.y; s.z += p.z; s.w += p.w;
    }
    int q = g_top[bh * U + u];
    int b = bh >> 3, h = bh & 7;
    *(float4*)&out[(size_t)(b * L + q) * HD + h * D + d4] = s;
}

// ------------------------------------------------------------------
extern "C" void kernel_launch(void* const* d_in, const int* in_sizes, int n_in,
                              void* d_out, int out_size) {
    const float* Q = (const float*)d_in[0];
    const float* K = (const float*)d_in[1];
    const float* V = (const float*)d_in[2];
    const int*  IS = (const int*)d_in[3];
    float* out = (float*)d_out;

    const int smem_probe  = 256 * 68 * 4;                  // 69632 (dynamic)
    const int smem_scores = (KT * 68 + U * 64) * 4;        // 79872
    const int smem_pv     = (KT * 64 + U * 260) * 4;       // 107136
    cudaFuncSetAttribute(k_probe8, cudaFuncAttributeMaxDynamicSharedMemorySize, smem_probe);
    cudaFuncSetAttribute(k_scores, cudaFuncAttributeMaxDynamicSharedMemorySize, smem_scores);
    cudaFuncSetAttribute(k_pv,     cudaFuncAttributeMaxDynamicSharedMemorySize, smem_pv);

    k_build  <<<(L + 255) / 256, 256>>>(IS);
    k_vmean  <<<BH, 256>>>(V);
    k_probe8 <<<dim3(L / QC2, BH), 256, smem_probe>>>(Q, K);
    k_topk4  <<<BH, 256>>>();
    k_fill   <<<(B * L * HD / 4) / 256, 256>>>(out);
    k_scores <<<dim3(L / KT, BH), 512, smem_scores>>>(Q, K);
    k_softmax<<<BH * U, 256>>>();
    k_pv     <<<dim3(L / KT, BH), 128, smem_pv>>>(V);
    k_final  <<<(BH * U * 16 + 255) / 256, 256>>>(out);
}

// round 8
// speedup vs baseline: 1.5857x; 1.3942x over previous
#include <cuda_runtime.h>
#include <cstddef>

#define B 8
#define L 2048
#define H 8
#define D 64
#define BH 64
#define SK 40
#define U  40
#define HD 512
#define SCALE 0.125f
#define KSPLIT 8        // pv key splits
#define KT 256          // scores/pv key tile

// ---- device scratch ----
__device__ float g_M[BH * L];
__device__ int   g_top[BH * U];
__device__ float g_vmean[BH * D];
__device__ float g_scores[(size_t)BH * U * L];
__device__ float g_pv[BH * KSPLIT * U * D];

// ------------------------------------------------------------------
// Probe (round-1 proven): M[b,h,q] = max_s(dot) - mean_s(dot).
// 2 queries per warp; 16 lanes per query, float4 per lane, 4-step
// half-warp reduce. L2-bandwidth bound (~124us measured in r1).
// ------------------------------------------------------------------
__global__ void k_probe_M(const float* __restrict__ Q, const float* __restrict__ Kp,
                          const int* __restrict__ IS) {
    int wg   = blockIdx.x * (blockDim.x >> 5) + (threadIdx.x >> 5);
    int lane = threadIdx.x & 31;
    int qh   = lane >> 4;        // which query in the pair
    int li   = lane & 15;        // lane within query group
    int qi   = wg * 2 + qh;      // 0 .. BH*L-1
    int bh   = qi >> 11;
    int q    = qi & (L - 1);
    int b = bh >> 3, h = bh & 7;

    float4 ql = *(const float4*)(Q + (size_t)(b * L + q) * HD + h * D + 4 * li);
    const int* isrow = IS + q * SK;
    float mx = -3.4e38f, sm = 0.f;
    #pragma unroll 4
    for (int s = 0; s < SK; ++s) {
        int idx = __ldg(isrow + s);
        float4 kv = *(const float4*)(Kp + (size_t)(b * L + idx) * HD + h * D + 4 * li);
        float p = ql.x * kv.x + ql.y * kv.y + ql.z * kv.z + ql.w * kv.w;
        p += __shfl_xor_sync(0xffffffffu, p, 8);
        p += __shfl_xor_sync(0xffffffffu, p, 4);
        p += __shfl_xor_sync(0xffffffffu, p, 2);
        p += __shfl_xor_sync(0xffffffffu, p, 1);
        mx = fmaxf(mx, p);
        sm += p;
    }
    if (li == 0) g_M[bh * L + q] = mx - sm * (1.f / SK);
}

// ------------------------------------------------------------------
// V mean per (b,h,d)
// ------------------------------------------------------------------
__global__ void k_vmean(const float* __restrict__ V) {
    __shared__ float smem[4 * 64];
    int bh = blockIdx.x; int b = bh >> 3, h = bh & 7;
    int d = threadIdx.x & 63, p = threadIdx.x >> 6;
    float s = 0.f;
    for (int l = p; l < L; l += 4)
        s += V[(size_t)(b * L + l) * HD + h * D + d];
    smem[p * 64 + d] = s;
    __syncthreads();
    if (threadIdx.x < 64) {
        float t = smem[threadIdx.x] + smem[64 + threadIdx.x]
                + smem[128 + threadIdx.x] + smem[192 + threadIdx.x];
        g_vmean[bh * 64 + threadIdx.x] = t * (1.f / L);
    }
}

// ------------------------------------------------------------------
// Top-40 per (b,h): phase 1 = 8 warps extract slice top-40 (regs);
// phase 2 = rank selection over 320 unique candidates (order-free:
// the output scatter is index-set based, so g_top order is irrelevant).
// ------------------------------------------------------------------
__global__ void k_topk4() {
    __shared__ unsigned long long cand[8 * U];
    int bh = blockIdx.x;
    int t = threadIdx.x, w = t >> 5, lane = t & 31;

    unsigned long long k[8];
    #pragma unroll
    for (int j = 0; j < 8; ++j) {
        int i = w * 256 + j * 32 + lane;
        unsigned bits = __float_as_uint(g_M[bh * L + i]);
        bits = (bits & 0x80000000u) ? ~bits : (bits | 0x80000000u);
        k[j] = ((unsigned long long)bits << 32) | (unsigned)(L - 1 - i);
    }
    for (int it = 0; it < U; ++it) {
        unsigned long long lm = k[0];
        #pragma unroll
        for (int j = 1; j < 8; ++j) if (k[j] > lm) lm = k[j];
        unsigned long long wm = lm;
        #pragma unroll
        for (int o = 16; o; o >>= 1) {
            unsigned long long x = __shfl_xor_sync(0xffffffffu, wm, o);
            if (x > wm) wm = x;
        }
        if (lane == 0) cand[w * U + it] = wm;
        #pragma unroll
        for (int j = 0; j < 8; ++j) if (k[j] == wm) k[j] = 0ull;
    }
    __syncthreads();
    for (int i = t; i < 8 * U; i += 256) {
        unsigned long long me = cand[i];
        int rank = 0;
        for (int j = 0; j < 8 * U; ++j) rank += (cand[j] > me) ? 1 : 0;
        if (rank < U)
            g_top[bh * U + rank] = (L - 1) - (int)(me & 0xffffffffu);
    }
}

// ------------------------------------------------------------------
// Fill output with broadcast V-mean
// ------------------------------------------------------------------
__global__ void k_fill(float* __restrict__ out) {
    int i4 = blockIdx.x * blockDim.x + threadIdx.x;
    int linear = i4 * 4;
    int d = linear & 63;
    int h = (linear >> 6) & 7;
    int b = linear >> 20;
    float4 v = *(const float4*)&g_vmean[(b * 8 + h) * 64 + d];
    *(float4*)(out + linear) = v;
}

// ------------------------------------------------------------------
// Scores: float4 smem reads, pitch 68 (conflict-free per phase)
// ------------------------------------------------------------------
__global__ void k_scores(const float* __restrict__ Q, const float* __restrict__ Kp) {
    extern __shared__ float smem[];
    float* Ksm = smem;               // KT * 68
    float* Qsm = smem + KT * 68;     // U * 64
    int bh = blockIdx.y, kt = blockIdx.x;
    int b = bh >> 3, h = bh & 7;
    int k0 = kt * KT;
    int t = threadIdx.x;             // 512

    for (int i4 = t; i4 < U * 16; i4 += 512) {
        int u = i4 >> 4, d4 = (i4 & 15) * 4;
        int qidx = g_top[bh * U + u];
        *(float4*)&Qsm[u * 64 + d4] =
            *(const float4*)&Q[(size_t)(b * L + qidx) * HD + h * D + d4];
    }
    for (int i4 = t; i4 < KT * 16; i4 += 512) {
        int k = i4 >> 4, d4 = (i4 & 15) * 4;
        *(float4*)&Ksm[k * 68 + d4] =
            *(const float4*)&Kp[(size_t)(b * L + k0 + k) * HD + h * D + d4];
    }
    __syncthreads();

    int kg = t & 63, ug = t >> 6;
    int u0 = ug * 5;
    float acc[5][4];
    #pragma unroll
    for (int i = 0; i < 5; ++i)
        #pragma unroll
        for (int j = 0; j < 4; ++j) acc[i][j] = 0.f;

    for (int d = 0; d < 64; d += 4) {
        float4 k4[4], q4[5];
        #pragma unroll
        for (int j = 0; j < 4; ++j) k4[j] = *(float4*)&Ksm[(kg + 64 * j) * 68 + d];
        #pragma unroll
        for (int i = 0; i < 5; ++i) q4[i] = *(float4*)&Qsm[(u0 + i) * 64 + d];
        #pragma unroll
        for (int i = 0; i < 5; ++i)
            #pragma unroll
            for (int j = 0; j < 4; ++j) {
                acc[i][j] = fmaf(q4[i].x, k4[j].x, acc[i][j]);
                acc[i][j] = fmaf(q4[i].y, k4[j].y, acc[i][j]);
                acc[i][j] = fmaf(q4[i].z, k4[j].z, acc[i][j]);
                acc[i][j] = fmaf(q4[i].w, k4[j].w, acc[i][j]);
            }
    }
    #pragma unroll
    for (int i = 0; i < 5; ++i)
        #pragma unroll
        for (int j = 0; j < 4; ++j)
            g_scores[(size_t)(bh * U + u0 + i) * L + k0 + kg + 64 * j] = acc[i][j] * SCALE;
}

// ------------------------------------------------------------------
// Row softmax over 2048, in place
// ------------------------------------------------------------------
__global__ void k_softmax() {
    __shared__ float red[8];
    size_t row = blockIdx.x;
    float* p = g_scores + row * L;
    int t = threadIdx.x, lane = t & 31, w = t >> 5;
    float4 v0 = *(float4*)&p[4 * t];
    float4 v1 = *(float4*)&p[4 * (t + 256)];
    float m = fmaxf(fmaxf(fmaxf(v0.x, v0.y), fmaxf(v0.z, v0.w)),
                    fmaxf(fmaxf(v1.x, v1.y), fmaxf(v1.z, v1.w)));
    #pragma unroll
    for (int o = 16; o; o >>= 1) m = fmaxf(m, __shfl_xor_sync(0xffffffffu, m, o));
    if (lane == 0) red[w] = m;
    __syncthreads();
    m = red[0];
    #pragma unroll
    for (int i = 1; i < 8; ++i) m = fmaxf(m, red[i]);
    __syncthreads();

    v0.x = __expf(v0.x - m); v0.y = __expf(v0.y - m);
    v0.z = __expf(v0.z - m); v0.w = __expf(v0.w - m);
    v1.x = __expf(v1.x - m); v1.y = __expf(v1.y - m);
    v1.z = __expf(v1.z - m); v1.w = __expf(v1.w - m);
    float s = v0.x + v0.y + v0.z + v0.w + v1.x + v1.y + v1.z + v1.w;
    #pragma unroll
    for (int o = 16; o; o >>= 1) s += __shfl_xor_sync(0xffffffffu, s, o);
    if (lane == 0) red[w] = s;
    __syncthreads();
    s = red[0];
    #pragma unroll
    for (int i = 1; i < 8; ++i) s += red[i];
    float inv = 1.f / s;
    v0.x *= inv; v0.y *= inv; v0.z *= inv; v0.w *= inv;
    v1.x *= inv; v1.y *= inv; v1.z *= inv; v1.w *= inv;
    *(float4*)&p[4 * t] = v0;
    *(float4*)&p[4 * (t + 256)] = v1;
}

// ------------------------------------------------------------------
// Partial PV per 256-key split
// ------------------------------------------------------------------
__global__ void k_pv(const float* __restrict__ V) {
    extern __shared__ float smem[];
    float* Vsm = smem;               // KT * 64
    float* Asm = smem + KT * 64;     // U * 260
    int bh = blockIdx.y, ks = blockIdx.x;
    int b = bh >> 3, h = bh & 7;
    int k0 = ks * KT;
    int t = threadIdx.x;             // 128

    for (int i4 = t; i4 < U * (KT / 4); i4 += 128) {
        int u = i4 >> 6, k4 = (i4 & 63) * 4;
        *(float4*)&Asm[u * 260 + k4] =
            *(const float4*)&g_scores[(size_t)(bh * U + u) * L + k0 + k4];
    }
    for (int i4 = t; i4 < KT * 16; i4 += 128) {
        int k = i4 >> 4, d4 = (i4 & 15) * 4;
        *(float4*)&Vsm[k * 64 + d4] =
            *(const float4*)&V[(size_t)(b * L + k0 + k) * HD + h * D + d4];
    }
    __syncthreads();

    int ug = t & 7, dg = t >> 3;
    int u0 = ug * 5, d0 = dg * 4;
    float4 acc[5];
    #pragma unroll
    for (int i = 0; i < 5; ++i) acc[i] = make_float4(0.f, 0.f, 0.f, 0.f);

    #pragma unroll 2
    for (int k = 0; k < KT; ++k) {
        float4 v = *(float4*)&Vsm[k * 64 + d0];
        #pragma unroll
        for (int i = 0; i < 5; ++i) {
            float a = Asm[(u0 + i) * 260 + k];
            acc[i].x = fmaf(a, v.x, acc[i].x);
            acc[i].y = fmaf(a, v.y, acc[i].y);
            acc[i].z = fmaf(a, v.z, acc[i].z);
            acc[i].w = fmaf(a, v.w, acc[i].w);
        }
    }
    #pragma unroll
    for (int i = 0; i < 5; ++i)
        *(float4*)&g_pv[(size_t)((bh * KSPLIT + ks) * U + u0 + i) * D + d0] = acc[i];
}

// ------------------------------------------------------------------
// Reduce partials, scatter to output
// ------------------------------------------------------------------
__global__ void k_final(float* __restrict__ out) {
    int i4 = blockIdx.x * blockDim.x + threadIdx.x;
    if (i4 >= BH * U * 16) return;
    int d4 = (i4 & 15) * 4;
    int u  = (i4 >> 4) % U;
    int bh = i4 / (U * 16);
    float4 s = make_float4(0.f, 0.f, 0.f, 0.f);
    #pragma unroll
    for (int ks = 0; ks < KSPLIT; ++ks) {
        float4 p = *(const float4*)&g_pv[(size_t)((bh * KSPLIT + ks) * U + u) * D + d4];
        s.x += p.x; s.y += p.y; s.z += p.z; s.w += p.w;
    }
    int q = g_top[bh * U + u];
    int b = bh >> 3, h = bh & 7;
    *(float4*)&out[(size_t)(b * L + q) * HD + h * D + d4] = s;
}

// ------------------------------------------------------------------
extern "C" void kernel_launch(void* const* d_in, const int* in_sizes, int n_in,
                              void* d_out, int out_size) {
    const float* Q = (const float*)d_in[0];
    const float* K = (const float*)d_in[1];
    const float* V = (const float*)d_in[2];
    const int*  IS = (const int*)d_in[3];
    float* out = (float*)d_out;

    const int smem_scores = (KT * 68 + U * 64) * 4;        // 79872
    const int smem_pv     = (KT * 64 + U * 260) * 4;       // 107136
    cudaFuncSetAttribute(k_scores, cudaFuncAttributeMaxDynamicSharedMemorySize, smem_scores);
    cudaFuncSetAttribute(k_pv,     cudaFuncAttributeMaxDynamicSharedMemorySize, smem_pv);

    k_probe_M<<<(BH * L / 2) / 8, 256>>>(Q, K, IS);        // 8192 blocks
    k_vmean  <<<BH, 256>>>(V);
    k_topk4  <<<BH, 256>>>();
    k_fill   <<<(B * L * HD / 4) / 256, 256>>>(out);
    k_scores <<<dim3(L / KT, BH), 512, smem_scores>>>(Q, K);
    k_softmax<<<BH * U, 256>>>();
    k_pv     <<<dim3(L / KT, BH), 128, smem_pv>>>(V);
    k_final  <<<(BH * U * 16 + 255) / 256, 256>>>(out);
}

// round 9
// speedup vs baseline: 1.6625x; 1.0485x over previous
#include <cuda_runtime.h>
#include <cstddef>

#define B 8
#define L 2048
#define H 8
#define D 64
#define BH 64
#define SK 40
#define U  40
#define HD 512
#define SCALE 0.125f
#define KS 16           // attention key splits
#define AKT 128         // attention key tile

// ---- device scratch ----
__device__ float g_M[BH * L];
__device__ int   g_top[BH * U];
__device__ float g_vmean[BH * D];
__device__ float g_pv[(size_t)BH * KS * 2 * U * D];  // 21 MB partial PV
__device__ float g_ml[BH * KS * U * 2];              // (m, l) per split

// ------------------------------------------------------------------
// Probe (r1-proven, L2-roofline bound ~124us): M = max_s - mean_s.
// 2 queries per warp; 16 lanes per query; 4-step half-warp reduce.
// ------------------------------------------------------------------
__global__ void k_probe_M(const float* __restrict__ Q, const float* __restrict__ Kp,
                          const int* __restrict__ IS) {
    int wg   = blockIdx.x * (blockDim.x >> 5) + (threadIdx.x >> 5);
    int lane = threadIdx.x & 31;
    int qh   = lane >> 4;
    int li   = lane & 15;
    int qi   = wg * 2 + qh;
    int bh   = qi >> 11;
    int q    = qi & (L - 1);
    int b = bh >> 3, h = bh & 7;

    float4 ql = *(const float4*)(Q + (size_t)(b * L + q) * HD + h * D + 4 * li);
    const int* isrow = IS + q * SK;
    float mx = -3.4e38f, sm = 0.f;
    #pragma unroll 4
    for (int s = 0; s < SK; ++s) {
        int idx = __ldg(isrow + s);
        float4 kv = *(const float4*)(Kp + (size_t)(b * L + idx) * HD + h * D + 4 * li);
        float p = ql.x * kv.x + ql.y * kv.y + ql.z * kv.z + ql.w * kv.w;
        p += __shfl_xor_sync(0xffffffffu, p, 8);
        p += __shfl_xor_sync(0xffffffffu, p, 4);
        p += __shfl_xor_sync(0xffffffffu, p, 2);
        p += __shfl_xor_sync(0xffffffffu, p, 1);
        mx = fmaxf(mx, p);
        sm += p;
    }
    if (li == 0) g_M[bh * L + q] = mx - sm * (1.f / SK);
}

// ------------------------------------------------------------------
// V mean per (b,h,d)
// ------------------------------------------------------------------
__global__ void k_vmean(const float* __restrict__ V) {
    __shared__ float smem[4 * 64];
    int bh = blockIdx.x; int b = bh >> 3, h = bh & 7;
    int d = threadIdx.x & 63, p = threadIdx.x >> 6;
    float s = 0.f;
    for (int l = p; l < L; l += 4)
        s += V[(size_t)(b * L + l) * HD + h * D + d];
    smem[p * 64 + d] = s;
    __syncthreads();
    if (threadIdx.x < 64) {
        float t = smem[threadIdx.x] + smem[64 + threadIdx.x]
                + smem[128 + threadIdx.x] + smem[192 + threadIdx.x];
        g_vmean[bh * 64 + threadIdx.x] = t * (1.f / L);
    }
}

// ------------------------------------------------------------------
// Top-40 per (b,h), 512 threads: 16 warps extract slice top-40 from
// 128 elements each (4 keys/lane), then rank-select over 640 unique
// candidates. g_top order is irrelevant (index-set scatter).
// ------------------------------------------------------------------
__global__ void k_topk5() {
    __shared__ unsigned long long cand[16 * U];   // 640 keys
    int bh = blockIdx.x;
    int t = threadIdx.x, w = t >> 5, lane = t & 31;

    unsigned long long k[4];
    #pragma unroll
    for (int j = 0; j < 4; ++j) {
        int i = w * 128 + j * 32 + lane;
        unsigned bits = __float_as_uint(g_M[bh * L + i]);
        bits = (bits & 0x80000000u) ? ~bits : (bits | 0x80000000u);
        k[j] = ((unsigned long long)bits << 32) | (unsigned)(L - 1 - i);
    }
    for (int it = 0; it < U; ++it) {
        unsigned long long lm = k[0];
        #pragma unroll
        for (int j = 1; j < 4; ++j) if (k[j] > lm) lm = k[j];
        unsigned long long wm = lm;
        #pragma unroll
        for (int o = 16; o; o >>= 1) {
            unsigned long long x = __shfl_xor_sync(0xffffffffu, wm, o);
            if (x > wm) wm = x;
        }
        if (lane == 0) cand[w * U + it] = wm;
        #pragma unroll
        for (int j = 0; j < 4; ++j) if (k[j] == wm) k[j] = 0ull;
    }
    __syncthreads();
    for (int i = t; i < 16 * U; i += 512) {
        unsigned long long me = cand[i];
        int rank = 0;
        #pragma unroll 4
        for (int j = 0; j < 16 * U; j += 2) {
            rank += (cand[j]     > me) ? 1 : 0;
            rank += (cand[j + 1] > me) ? 1 : 0;
        }
        if (rank < U)
            g_top[bh * U + rank] = (L - 1) - (int)(me & 0xffffffffu);
    }
}

// ------------------------------------------------------------------
// Fill output with broadcast V-mean
// ------------------------------------------------------------------
__global__ void k_fill(float* __restrict__ out) {
    int i4 = blockIdx.x * blockDim.x + threadIdx.x;
    int linear = i4 * 4;
    int d = linear & 63;
    int h = (linear >> 6) & 7;
    int b = linear >> 20;
    float4 v = *(const float4*)&g_vmean[(b * 8 + h) * 64 + d];
    *(float4*)(out + linear) = v;
}

// ------------------------------------------------------------------
// Fused scores + partial softmax + PV (flash split-K). r2-verified.
// Block = (ks, bh), 128 keys per block.
// ------------------------------------------------------------------
__global__ __launch_bounds__(256, 2) void k_attn(const float* __restrict__ Q,
                                                 const float* __restrict__ Kp,
                                                 const float* __restrict__ V) {
    extern __shared__ float smem[];
    float* Qsm  = smem;            // 40*64  = 2560
    float* KVsm = smem + 2560;     // 128*68 = 8704
    float* Asm  = KVsm + 8704;     // 40*132 = 5280
    int bh = blockIdx.y, ks = blockIdx.x;
    int b = bh >> 3, h = bh & 7;
    int k0 = ks * AKT;
    int t = threadIdx.x;

    for (int i = t; i < U * 16; i += 256) {
        int u = i >> 4, dq = i & 15;
        int qi = g_top[bh * U + u];
        *(float4*)&Qsm[u * 64 + dq * 4] =
            *(const float4*)&Q[(size_t)(b * L + qi) * HD + h * D + dq * 4];
    }
    for (int i = t; i < AKT * 16; i += 256) {
        int r = i >> 4, dq = i & 15;
        *(float4*)&KVsm[r * 68 + dq * 4] =
            *(const float4*)&Kp[(size_t)(b * L + k0 + r) * HD + h * D + dq * 4];
    }
    __syncthreads();

    // scores: thread = (kg 0..63, ug 0..3); k = kg, kg+64; u = ug*10..+9
    {
        int kg = t & 63, ug = t >> 6;
        float acc[10][2];
        #pragma unroll
        for (int i = 0; i < 10; ++i) { acc[i][0] = 0.f; acc[i][1] = 0.f; }
        for (int d = 0; d < 64; d += 4) {
            float4 ka = *(float4*)&KVsm[kg * 68 + d];
            float4 kb = *(float4*)&KVsm[(kg + 64) * 68 + d];
            #pragma unroll
            for (int i = 0; i < 10; ++i) {
                float4 q4 = *(float4*)&Qsm[(ug * 10 + i) * 64 + d];
                acc[i][0] = fmaf(q4.x, ka.x, acc[i][0]);
                acc[i][0] = fmaf(q4.y, ka.y, acc[i][0]);
                acc[i][0] = fmaf(q4.z, ka.z, acc[i][0]);
                acc[i][0] = fmaf(q4.w, ka.w, acc[i][0]);
                acc[i][1] = fmaf(q4.x, kb.x, acc[i][1]);
                acc[i][1] = fmaf(q4.y, kb.y, acc[i][1]);
                acc[i][1] = fmaf(q4.z, kb.z, acc[i][1]);
                acc[i][1] = fmaf(q4.w, kb.w, acc[i][1]);
            }
        }
        #pragma unroll
        for (int i = 0; i < 10; ++i) {
            Asm[(ug * 10 + i) * 132 + kg]      = acc[i][0] * SCALE;
            Asm[(ug * 10 + i) * 132 + kg + 64] = acc[i][1] * SCALE;
        }
    }
    __syncthreads();

    // V -> KVsm (overlapped with stats); per-row (m, l) stats
    for (int i = t; i < AKT * 16; i += 256) {
        int r = i >> 4, dq = i & 15;
        *(float4*)&KVsm[r * 68 + dq * 4] =
            *(const float4*)&V[(size_t)(b * L + k0 + r) * HD + h * D + dq * 4];
    }
    {
        int w = t >> 5, lane = t & 31;
        #pragma unroll
        for (int rr = 0; rr < 5; ++rr) {
            int u = w * 5 + rr;
            float vals[4], m = -3.4e38f;
            #pragma unroll
            for (int mm = 0; mm < 4; ++mm) {
                vals[mm] = Asm[u * 132 + lane + 32 * mm];
                m = fmaxf(m, vals[mm]);
            }
            #pragma unroll
            for (int o = 16; o; o >>= 1) m = fmaxf(m, __shfl_xor_sync(0xffffffffu, m, o));
            float lsum = 0.f;
            #pragma unroll
            for (int mm = 0; mm < 4; ++mm) {
                float pe = __expf(vals[mm] - m);
                Asm[u * 132 + lane + 32 * mm] = pe;
                lsum += pe;
            }
            #pragma unroll
            for (int o = 16; o; o >>= 1) lsum += __shfl_xor_sync(0xffffffffu, lsum, o);
            if (lane == 0) {
                g_ml[((bh * KS + ks) * U + u) * 2 + 0] = m;
                g_ml[((bh * KS + ks) * U + u) * 2 + 1] = lsum;
            }
        }
    }
    __syncthreads();

    // PV: thread = (kh 0..1, ug2 0..7, dg 0..15); 5u x 4d over 64 k
    {
        int kh = t >> 7, ug2 = (t >> 4) & 7, dg = t & 15;
        int kb = kh * 64;
        float4 o[5];
        #pragma unroll
        for (int i = 0; i < 5; ++i) o[i] = make_float4(0.f, 0.f, 0.f, 0.f);
        for (int k = 0; k < 64; ++k) {
            float4 v = *(float4*)&KVsm[(kb + k) * 68 + dg * 4];
            #pragma unroll
            for (int i = 0; i < 5; ++i) {
                float a = Asm[(ug2 * 5 + i) * 132 + kb + k];
                o[i].x = fmaf(a, v.x, o[i].x);
                o[i].y = fmaf(a, v.y, o[i].y);
                o[i].z = fmaf(a, v.z, o[i].z);
                o[i].w = fmaf(a, v.w, o[i].w);
            }
        }
        #pragma unroll
        for (int i = 0; i < 5; ++i)
            *(float4*)&g_pv[(size_t)(((bh * KS + ks) * 2 + kh) * U + ug2 * 5 + i) * D + dg * 4] = o[i];
    }
}

// ------------------------------------------------------------------
// Combine split-K partials with softmax rescale, scatter to output
// ------------------------------------------------------------------
__global__ void k_final(float* __restrict__ out) {
    int i4 = blockIdx.x * blockDim.x + threadIdx.x;
    if (i4 >= BH * U * 16) return;
    int dq = i4 & 15;
    int u  = (i4 >> 4) % U;
    int bh = i4 / (U * 16);

    float mv[KS], lv[KS], M = -3.4e38f;
    #pragma unroll
    for (int s = 0; s < KS; ++s) {
        mv[s] = g_ml[((bh * KS + s) * U + u) * 2 + 0];
        lv[s] = g_ml[((bh * KS + s) * U + u) * 2 + 1];
        M = fmaxf(M, mv[s]);
    }
    float4 acc = make_float4(0.f, 0.f, 0.f, 0.f);
    float lsum = 0.f;
    #pragma unroll
    for (int s = 0; s < KS; ++s) {
        float wgt = __expf(mv[s] - M);
        lsum += wgt * lv[s];
        float4 p0 = *(const float4*)&g_pv[(size_t)(((bh * KS + s) * 2 + 0) * U + u) * D + dq * 4];
        float4 p1 = *(const float4*)&g_pv[(size_t)(((bh * KS + s) * 2 + 1) * U + u) * D + dq * 4];
        acc.x = fmaf(wgt, p0.x + p1.x, acc.x);
        acc.y = fmaf(wgt, p0.y + p1.y, acc.y);
        acc.z = fmaf(wgt, p0.z + p1.z, acc.z);
        acc.w = fmaf(wgt, p0.w + p1.w, acc.w);
    }
    float inv = 1.f / lsum;
    int q = g_top[bh * U + u];
    int b = bh >> 3, h = bh & 7;
    *(float4*)&out[(size_t)(b * L + q) * HD + h * D + dq * 4] =
        make_float4(acc.x * inv, acc.y * inv, acc.z * inv, acc.w * inv);
}

// ------------------------------------------------------------------
extern "C" void kernel_launch(void* const* d_in, const int* in_sizes, int n_in,
                              void* d_out, int out_size) {
    const float* Q = (const float*)d_in[0];
    const float* K = (const float*)d_in[1];
    const float* V = (const float*)d_in[2];
    const int*  IS = (const int*)d_in[3];
    float* out = (float*)d_out;

    const int smem_attn = (2560 + 8704 + 5280) * 4;   // 66176
    cudaFuncSetAttribute(k_attn, cudaFuncAttributeMaxDynamicSharedMemorySize, smem_attn);

    k_probe_M<<<(BH * L / 2) / 8, 256>>>(Q, K, IS);   // 8192 blocks
    k_vmean  <<<BH, 256>>>(V);
    k_topk5  <<<BH, 512>>>();
    k_fill   <<<(B * L * HD / 4) / 256, 256>>>(out);
    k_attn   <<<dim3(KS, BH), 256, smem_attn>>>(Q, K, V);
    k_final  <<<(BH * U * 16 + 255) / 256, 256>>>(out);
}

// round 10
// speedup vs baseline: 1.8641x; 1.1213x over previous
#include <cuda_runtime.h>
#include <cstddef>

#define B 8
#define L 2048
#define H 8
#define D 64
#define BH 64
#define SK 40
#define U  40
#define HD 512
#define SCALE 0.125f
#define KS 16           // attention key splits
#define AKT 128         // attention key tile
#define FILLB 32        // fill slabs per bh (64 rows each)

// ---- device scratch ----
__device__ float g_M[BH * L];
__device__ int   g_top[BH * U];
__device__ float g_vmean[BH * D];
__device__ float g_pv[(size_t)BH * KS * 2 * U * D];  // partial PV
__device__ float g_ml[BH * KS * U * 2];              // (m, l) per split

// ------------------------------------------------------------------
// Probe (L2-roofline bound ~124us): M = max_s - mean_s.
// 2 queries per warp; 16 lanes per query; 4-step half-warp reduce.
// ------------------------------------------------------------------
__global__ void k_probe_M(const float* __restrict__ Q, const float* __restrict__ Kp,
                          const int* __restrict__ IS) {
    int wg   = blockIdx.x * (blockDim.x >> 5) + (threadIdx.x >> 5);
    int lane = threadIdx.x & 31;
    int qh   = lane >> 4;
    int li   = lane & 15;
    int qi   = wg * 2 + qh;
    int bh   = qi >> 11;
    int q    = qi & (L - 1);
    int b = bh >> 3, h = bh & 7;

    float4 ql = *(const float4*)(Q + (size_t)(b * L + q) * HD + h * D + 4 * li);
    const int* isrow = IS + q * SK;
    float mx = -3.4e38f, sm = 0.f;
    #pragma unroll 4
    for (int s = 0; s < SK; ++s) {
        int idx = __ldg(isrow + s);
        float4 kv = *(const float4*)(Kp + (size_t)(b * L + idx) * HD + h * D + 4 * li);
        float p = ql.x * kv.x + ql.y * kv.y + ql.z * kv.z + ql.w * kv.w;
        p += __shfl_xor_sync(0xffffffffu, p, 8);
        p += __shfl_xor_sync(0xffffffffu, p, 4);
        p += __shfl_xor_sync(0xffffffffu, p, 2);
        p += __shfl_xor_sync(0xffffffffu, p, 1);
        mx = fmaxf(mx, p);
        sm += p;
    }
    if (li == 0) g_M[bh * L + q] = mx - sm * (1.f / SK);
}

// ------------------------------------------------------------------
// phase2: blocks 0-63 = top-40 per bh; blocks 64-127 = V mean per bh.
// topk: 16 warps x 128-elem slices (4 keys/lane) -> rank-select over
// 640 unique candidates (g_top order irrelevant: index-set scatter).
// ------------------------------------------------------------------
__global__ __launch_bounds__(512) void k_phase2(const float* __restrict__ V) {
    __shared__ unsigned long long cand[16 * U];   // topk
    __shared__ float vsm[8 * 64];                 // vmean
    int bh = blockIdx.x & 63;
    int role = blockIdx.x >> 6;
    int t = threadIdx.x;

    if (role == 1) {      // ---- vmean ----
        int b = bh >> 3, h = bh & 7;
        int d = t & 63, p = t >> 6;   // p 0..7
        float s = 0.f;
        for (int l = p; l < L; l += 8)
            s += V[(size_t)(b * L + l) * HD + h * D + d];
        vsm[p * 64 + d] = s;
        __syncthreads();
        if (t < 64) {
            float acc = 0.f;
            #pragma unroll
            for (int i = 0; i < 8; ++i) acc += vsm[i * 64 + t];
            g_vmean[bh * 64 + t] = acc * (1.f / L);
        }
        return;
    }

    // ---- topk ----
    int w = t >> 5, lane = t & 31;
    unsigned long long k[4];
    #pragma unroll
    for (int j = 0; j < 4; ++j) {
        int i = w * 128 + j * 32 + lane;
        unsigned bits = __float_as_uint(g_M[bh * L + i]);
        bits = (bits & 0x80000000u) ? ~bits : (bits | 0x80000000u);
        k[j] = ((unsigned long long)bits << 32) | (unsigned)(L - 1 - i);
    }
    for (int it = 0; it < U; ++it) {
        unsigned long long lm = k[0];
        #pragma unroll
        for (int j = 1; j < 4; ++j) if (k[j] > lm) lm = k[j];
        unsigned long long wm = lm;
        #pragma unroll
        for (int o = 16; o; o >>= 1) {
            unsigned long long x = __shfl_xor_sync(0xffffffffu, wm, o);
            if (x > wm) wm = x;
        }
        if (lane == 0) cand[w * U + it] = wm;
        #pragma unroll
        for (int j = 0; j < 4; ++j) if (k[j] == wm) k[j] = 0ull;
    }
    __syncthreads();
    for (int i = t; i < 16 * U; i += 512) {
        unsigned long long me = cand[i];
        int rank = 0;
        #pragma unroll 4
        for (int j = 0; j < 16 * U; j += 2) {
            rank += (cand[j]     > me) ? 1 : 0;
            rank += (cand[j + 1] > me) ? 1 : 0;
        }
        if (rank < U)
            g_top[bh * U + rank] = (L - 1) - (int)(me & 0xffffffffu);
    }
}

// ------------------------------------------------------------------
// phase3: blockIdx.x < KS  -> fused scores+softmax+PV split (r2/r9
// verified numerics, unchanged); blockIdx.x >= KS -> fill a 64-row
// slab of the output with broadcast V-mean (hidden under attn).
// ------------------------------------------------------------------
__global__ __launch_bounds__(256, 3) void k_phase3(const float* __restrict__ Q,
                                                   const float* __restrict__ Kp,
                                                   const float* __restrict__ V,
                                                   float* __restrict__ out) {
    extern __shared__ float smem[];
    int bh = blockIdx.y;
    int b = bh >> 3, h = bh & 7;
    int t = threadIdx.x;

    if (blockIdx.x >= KS) {    // ---- fill slab ----
        int j = blockIdx.x - KS;          // 0..31
        int l0 = j * 64;
        const float4* vm4 = (const float4*)&g_vmean[bh * 64];
        float4* out4 = (float4*)out;
        #pragma unroll
        for (int kk = 0; kk < 4; ++kk) {
            int fi  = t + kk * 256;       // 0..1023
            int row = fi >> 4, c4 = fi & 15;
            out4[(size_t)(b * L + l0 + row) * (HD / 4) + h * 16 + c4] = vm4[c4];
        }
        return;
    }

    // ---- attn split ----
    float* Qsm  = smem;            // 40*64  = 2560
    float* KVsm = smem + 2560;     // 128*68 = 8704
    float* Asm  = KVsm + 8704;     // 40*132 = 5280
    int ks = blockIdx.x;
    int k0 = ks * AKT;

    for (int i = t; i < U * 16; i += 256) {
        int u = i >> 4, dq = i & 15;
        int qi = g_top[bh * U + u];
        *(float4*)&Qsm[u * 64 + dq * 4] =
            *(const float4*)&Q[(size_t)(b * L + qi) * HD + h * D + dq * 4];
    }
    for (int i = t; i < AKT * 16; i += 256) {
        int r = i >> 4, dq = i & 15;
        *(float4*)&KVsm[r * 68 + dq * 4] =
            *(const float4*)&Kp[(size_t)(b * L + k0 + r) * HD + h * D + dq * 4];
    }
    __syncthreads();

    {   // scores: thread = (kg 0..63, ug 0..3)
        int kg = t & 63, ug = t >> 6;
        float acc[10][2];
        #pragma unroll
        for (int i = 0; i < 10; ++i) { acc[i][0] = 0.f; acc[i][1] = 0.f; }
        for (int d = 0; d < 64; d += 4) {
            float4 ka = *(float4*)&KVsm[kg * 68 + d];
            float4 kb = *(float4*)&KVsm[(kg + 64) * 68 + d];
            #pragma unroll
            for (int i = 0; i < 10; ++i) {
                float4 q4 = *(float4*)&Qsm[(ug * 10 + i) * 64 + d];
                acc[i][0] = fmaf(q4.x, ka.x, acc[i][0]);
                acc[i][0] = fmaf(q4.y, ka.y, acc[i][0]);
                acc[i][0] = fmaf(q4.z, ka.z, acc[i][0]);
                acc[i][0] = fmaf(q4.w, ka.w, acc[i][0]);
                acc[i][1] = fmaf(q4.x, kb.x, acc[i][1]);
                acc[i][1] = fmaf(q4.y, kb.y, acc[i][1]);
                acc[i][1] = fmaf(q4.z, kb.z, acc[i][1]);
                acc[i][1] = fmaf(q4.w, kb.w, acc[i][1]);
            }
        }
        #pragma unroll
        for (int i = 0; i < 10; ++i) {
            Asm[(ug * 10 + i) * 132 + kg]      = acc[i][0] * SCALE;
            Asm[(ug * 10 + i) * 132 + kg + 64] = acc[i][1] * SCALE;
        }
    }
    __syncthreads();

    // V -> KVsm (overlapped with stats); per-row (m, l) stats
    for (int i = t; i < AKT * 16; i += 256) {
        int r = i >> 4, dq = i & 15;
        *(float4*)&KVsm[r * 68 + dq * 4] =
            *(const float4*)&V[(size_t)(b * L + k0 + r) * HD + h * D + dq * 4];
    }
    {
        int w = t >> 5, lane = t & 31;
        #pragma unroll
        for (int rr = 0; rr < 5; ++rr) {
            int u = w * 5 + rr;
            float vals[4], m = -3.4e38f;
            #pragma unroll
            for (int mm = 0; mm < 4; ++mm) {
                vals[mm] = Asm[u * 132 + lane + 32 * mm];
                m = fmaxf(m, vals[mm]);
            }
            #pragma unroll
            for (int o = 16; o; o >>= 1) m = fmaxf(m, __shfl_xor_sync(0xffffffffu, m, o));
            float lsum = 0.f;
            #pragma unroll
            for (int mm = 0; mm < 4; ++mm) {
                float pe = __expf(vals[mm] - m);
                Asm[u * 132 + lane + 32 * mm] = pe;
                lsum += pe;
            }
            #pragma unroll
            for (int o = 16; o; o >>= 1) lsum += __shfl_xor_sync(0xffffffffu, lsum, o);
            if (lane == 0) {
                g_ml[((bh * KS + ks) * U + u) * 2 + 0] = m;
                g_ml[((bh * KS + ks) * U + u) * 2 + 1] = lsum;
            }
        }
    }
    __syncthreads();

    {   // PV: thread = (kh 0..1, ug2 0..7, dg 0..15)
        int kh = t >> 7, ug2 = (t >> 4) & 7, dg = t & 15;
        int kb = kh * 64;
        float4 o[5];
        #pragma unroll
        for (int i = 0; i < 5; ++i) o[i] = make_float4(0.f, 0.f, 0.f, 0.f);
        for (int k = 0; k < 64; ++k) {
            float4 v = *(float4*)&KVsm[(kb + k) * 68 + dg * 4];
            #pragma unroll
            for (int i = 0; i < 5; ++i) {
                float a = Asm[(ug2 * 5 + i) * 132 + kb + k];
                o[i].x = fmaf(a, v.x, o[i].x);
                o[i].y = fmaf(a, v.y, o[i].y);
                o[i].z = fmaf(a, v.z, o[i].z);
                o[i].w = fmaf(a, v.w, o[i].w);
            }
        }
        #pragma unroll
        for (int i = 0; i < 5; ++i)
            *(float4*)&g_pv[(size_t)(((bh * KS + ks) * 2 + kh) * U + ug2 * 5 + i) * D + dg * 4] = o[i];
    }
}

// ------------------------------------------------------------------
// Combine split-K partials with softmax rescale, scatter to output
// ------------------------------------------------------------------
__global__ void k_final(float* __restrict__ out) {
    int i4 = blockIdx.x * blockDim.x + threadIdx.x;
    if (i4 >= BH * U * 16) return;
    int dq = i4 & 15;
    int u  = (i4 >> 4) % U;
    int bh = i4 / (U * 16);

    float mv[KS], lv[KS], M = -3.4e38f;
    #pragma unroll
    for (int s = 0; s < KS; ++s) {
        mv[s] = g_ml[((bh * KS + s) * U + u) * 2 + 0];
        lv[s] = g_ml[((bh * KS + s) * U + u) * 2 + 1];
        M = fmaxf(M, mv[s]);
    }
    float4 acc = make_float4(0.f, 0.f, 0.f, 0.f);
    float lsum = 0.f;
    #pragma unroll
    for (int s = 0; s < KS; ++s) {
        float wgt = __expf(mv[s] - M);
        lsum += wgt * lv[s];
        float4 p0 = *(const float4*)&g_pv[(size_t)(((bh * KS + s) * 2 + 0) * U + u) * D + dq * 4];
        float4 p1 = *(const float4*)&g_pv[(size_t)(((bh * KS + s) * 2 + 1) * U + u) * D + dq * 4];
        acc.x = fmaf(wgt, p0.x + p1.x, acc.x);
        acc.y = fmaf(wgt, p0.y + p1.y, acc.y);
        acc.z = fmaf(wgt, p0.z + p1.z, acc.z);
        acc.w = fmaf(wgt, p0.w + p1.w, acc.w);
    }
    float inv = 1.f / lsum;
    int q = g_top[bh * U + u];
    int b = bh >> 3, h = bh & 7;
    *(float4*)&out[(size_t)(b * L + q) * HD + h * D + dq * 4] =
        make_float4(acc.x * inv, acc.y * inv, acc.z * inv, acc.w * inv);
}

// ------------------------------------------------------------------
extern "C" void kernel_launch(void* const* d_in, const int* in_sizes, int n_in,
                              void* d_out, int out_size) {
    const float* Q = (const float*)d_in[0];
    const float* K = (const float*)d_in[1];
    const float* V = (const float*)d_in[2];
    const int*  IS = (const int*)d_in[3];
    float* out = (float*)d_out;

    const int smem_attn = (2560 + 8704 + 5280) * 4;   // 66176
    cudaFuncSetAttribute(k_phase3, cudaFuncAttributeMaxDynamicSharedMemorySize, smem_attn);

    k_probe_M<<<(BH * L / 2) / 8, 256>>>(Q, K, IS);                 // 8192 blocks
    k_phase2 <<<128, 512>>>(V);                                     // topk || vmean
    k_phase3 <<<dim3(KS + FILLB, BH), 256, smem_attn>>>(Q, K, V, out); // attn || fill
    k_final  <<<(BH * U * 16 + 255) / 256, 256>>>(out);
}